// round 14
// baseline (speedup 1.0000x reference)
#include <cuda_runtime.h>
#include <cuda_fp16.h>
#include <cstdint>

#define Bn 16
#define Qn 2048
#define Kn 2048
#define Dn 128
#define QT 128
#define KT 64
#define NKT 32
#define NTHREADS 256
#define SCALE 0.08838834764831845f

// smem: fp16 K/V tiles 256B rows, XOR swizzle (c16 ^= r&7)
#define SQ_OFF 0            // Q: 128 x 256B = 32768
#define SK_OFF 32768        // K: 4 bufs x 16384 = 65536
#define SV_OFF 98304        // V: 4 bufs x 16384 = 65536
#define SP_OFF 163840       // P: 128 x 128B = 16384 (fp16, swizzled)
#define SL_OFF 180224       // l partials: 2 x 128 floats = 1024
#define SMEM_TOTAL 181248
#define KBUF 16384

__device__ __half KH[(size_t)Bn * Kn * Dn];
__device__ __half VH[(size_t)Bn * Kn * Dn];
__device__ float g_meanV[Bn * Dn];            // per-batch column SUMS of V

// ------------------------------------------------------------------ helpers
__device__ __forceinline__ uint32_t smem_u32(const void* p) {
    uint32_t a;
    asm("{ .reg .u64 t; cvta.to.shared.u64 t, %1; cvt.u32.u64 %0, t; }"
        : "=r"(a) : "l"(p));
    return a;
}
__device__ __forceinline__ float ex2f(float x) {
    float y; asm("ex2.approx.ftz.f32 %0, %1;" : "=f"(y) : "f"(x)); return y;
}
__device__ __forceinline__ uint32_t pack_h2(float lo, float hi) {
    __half2 h = __floats2half2_rn(lo, hi);
    return *reinterpret_cast<uint32_t*>(&h);
}
// fp32-accum (PV)
__device__ __forceinline__ void mma16(float* c, const uint32_t* a,
                                      uint32_t b0, uint32_t b1) {
    asm volatile(
        "mma.sync.aligned.m16n8k16.row.col.f32.f16.f16.f32 "
        "{%0,%1,%2,%3}, {%4,%5,%6,%7}, {%8,%9}, {%0,%1,%2,%3};\n"
        : "+f"(c[0]), "+f"(c[1]), "+f"(c[2]), "+f"(c[3])
        : "r"(a[0]), "r"(a[1]), "r"(a[2]), "r"(a[3]), "r"(b0), "r"(b1));
}
// fp16-accum (QK: S accumulates over only D=128 -> 8 roundings, safe)
__device__ __forceinline__ void mma16h(uint32_t* c, const uint32_t* a,
                                       uint32_t b0, uint32_t b1) {
    asm volatile(
        "mma.sync.aligned.m16n8k16.row.col.f16.f16.f16.f16 "
        "{%0,%1}, {%2,%3,%4,%5}, {%6,%7}, {%0,%1};\n"
        : "+r"(c[0]), "+r"(c[1])
        : "r"(a[0]), "r"(a[1]), "r"(a[2]), "r"(a[3]), "r"(b0), "r"(b1));
}
__device__ __forceinline__ void ldsm4(uint32_t* r, uint32_t addr) {
    asm volatile("ldmatrix.sync.aligned.m8n8.x4.shared.b16 {%0,%1,%2,%3}, [%4];"
                 : "=r"(r[0]), "=r"(r[1]), "=r"(r[2]), "=r"(r[3]) : "r"(addr));
}
__device__ __forceinline__ void ldsm4t(uint32_t* r, uint32_t addr) {
    asm volatile("ldmatrix.sync.aligned.m8n8.x4.trans.shared.b16 {%0,%1,%2,%3}, [%4];"
                 : "=r"(r[0]), "=r"(r[1]), "=r"(r[2]), "=r"(r[3]) : "r"(addr));
}
__device__ __forceinline__ void cpa16(uint32_t dst, const void* src) {
    asm volatile("cp.async.cg.shared.global [%0], [%1], 16;"
                 :: "r"(dst), "l"(src) : "memory");
}
#define CP_COMMIT() asm volatile("cp.async.commit_group;" ::: "memory")
#define CP_WAIT2()  asm volatile("cp.async.wait_group 2;"  ::: "memory")
#define PAIR_BAR(id) asm volatile("bar.sync %0, 64;" :: "r"(id) : "memory")

// ------------------------------------------------------------------ prep
__global__ void convert_kernel(const float* __restrict__ K,
                               const float* __restrict__ V) {
    __shared__ float sh[128];
    const int tid = threadIdx.x;
    if (tid < 128) sh[tid] = 0.0f;
    __syncthreads();

    const size_t i = (size_t)blockIdx.x * 256 + tid;   // float4 index
    float4 k4 = reinterpret_cast<const float4*>(K)[i];
    float4 v4 = reinterpret_cast<const float4*>(V)[i];
    uint2 uk = { pack_h2(k4.x, k4.y), pack_h2(k4.z, k4.w) };
    uint2 uv = { pack_h2(v4.x, v4.y), pack_h2(v4.z, v4.w) };
    reinterpret_cast<uint2*>(KH)[i] = uk;
    reinterpret_cast<uint2*>(VH)[i] = uv;

    const int c = ((int)(i & 31)) * 4;
    atomicAdd(&sh[c],     v4.x);
    atomicAdd(&sh[c + 1], v4.y);
    atomicAdd(&sh[c + 2], v4.z);
    atomicAdd(&sh[c + 3], v4.w);
    __syncthreads();

    if (tid < 128)
        atomicAdd(&g_meanV[(blockIdx.x >> 8) * 128 + tid], sh[tid]);
}

// ------------------------------------------------------------------ flash
// CTA = (128-q tile, batch). wm = warp>>1, wn = warp&1 (pairs on adjacent
// SMSPs, named pair barrier for P exchange). QK fp16-accum, PV fp32-accum.
__global__ void __launch_bounds__(NTHREADS, 1)
flash_kernel(const float* __restrict__ Qg, const int* __restrict__ VL,
             float* __restrict__ Og)
{
    const int b    = blockIdx.y;
    const int q0   = blockIdx.x * QT;
    const int tid  = threadIdx.x;
    const int warp = tid >> 5;
    const int wm   = warp >> 1;
    const int wn   = warp & 1;
    const int lane = tid & 31;
    const int g    = lane >> 2;
    const int t    = lane & 3;
    const int l7   = lane & 7;
    const int b3   = (lane >> 3) & 1;
    const int hi   = lane >> 4;
    const int vl   = VL[b];
    const float invK = 1.0f / (float)Kn;
    float* Ob = Og + ((size_t)b * Qn + q0) * Dn;

    if (q0 >= vl) {
        for (int r = warp; r < QT; r += 8) {
            int c = lane * 4;
            float4 m = *reinterpret_cast<const float4*>(&g_meanV[b * Dn + c]);
            m.x *= invK; m.y *= invK; m.z *= invK; m.w *= invK;
            *reinterpret_cast<float4*>(&Ob[(size_t)r * Dn + c]) = m;
        }
        return;
    }

    extern __shared__ char smem[];
    const uint32_t sb = smem_u32(smem);
    float* sL = reinterpret_cast<float*>(smem + SL_OFF);
    const __half* Kb = KH + (size_t)b * Kn * Dn;
    const __half* Vb = VH + (size_t)b * Kn * Dn;

#define ISSUE_TILE(kt_, bf_) do {                                              \
        const __half* ks_ = Kb + (size_t)(kt_) * KT * Dn;                       \
        const __half* vs_ = Vb + (size_t)(kt_) * KT * Dn;                       \
        _Pragma("unroll")                                                       \
        for (int j_ = 0; j_ < 4; j_++) {                                        \
            int id_ = j_ * 256 + tid;                                           \
            int r_ = id_ >> 4, c_ = id_ & 15;                                   \
            uint32_t off_ = (uint32_t)(r_ * 256 + ((c_ ^ (r_ & 7)) << 4));      \
            cpa16(sb + SK_OFF + (bf_) * KBUF + off_, ks_ + r_ * 128 + c_ * 8);  \
            cpa16(sb + SV_OFF + (bf_) * KBUF + off_, vs_ + r_ * 128 + c_ * 8);  \
        }                                                                       \
    } while (0)

    ISSUE_TILE(0, 0); CP_COMMIT();
    ISSUE_TILE(1, 1); CP_COMMIT();
    ISSUE_TILE(2, 2); CP_COMMIT();
    {
        const float4* Qs = reinterpret_cast<const float4*>(
            Qg + ((size_t)b * Qn + q0) * Dn);
#pragma unroll
        for (int j = 0; j < 16; j++) {
            int f = j * 256 + tid;
            int row = f >> 5, d4 = f & 31;
            float4 x = Qs[f];
            uint2 u = { pack_h2(x.x, x.y), pack_h2(x.z, x.w) };
            int c16 = d4 >> 1;
            uint32_t byte = (uint32_t)(row * 256 + ((c16 ^ (row & 7)) << 4)
                                       + (d4 & 1) * 8);
            *reinterpret_cast<uint2*>(smem + SQ_OFF + byte) = u;
        }
    }
    __syncthreads();

    uint32_t qa[2][8][4];
#pragma unroll
    for (int mb = 0; mb < 2; mb++) {
        const uint32_t qrow = sb + SQ_OFF
            + (uint32_t)((wm * 32 + mb * 16 + b3 * 8 + l7) * 256);
#pragma unroll
        for (int kk = 0; kk < 8; kk++)
            ldsm4(qa[mb][kk], qrow + (uint32_t)(((2 * kk + hi) ^ l7) << 4));
    }

    const uint32_t krow = (uint32_t)((hi * 8 + l7) * 256) + (uint32_t)(wn * 8192);
    const uint32_t vrow = (uint32_t)((b3 * 8 + l7) * 256);
    const uint32_t prow = sb + SP_OFF + (uint32_t)((wm * 32 + b3 * 8 + l7) * 128);

    const float C1 = SCALE * 1.4426950408889634f;
    const float C2 = -8.0f * 1.4426950408889634f;

    float od[2][8][4];
#pragma unroll
    for (int mb = 0; mb < 2; mb++)
#pragma unroll
        for (int i = 0; i < 8; i++)
            od[mb][i][0] = od[mb][i][1] = od[mb][i][2] = od[mb][i][3] = 0.f;
    float lacc[2][2] = {{0.f, 0.f}, {0.f, 0.f}};

    for (int kt = 0; kt < NKT; kt++) {
        const int buf = kt & 3;
        const uint32_t sKb = sb + SK_OFF + buf * KBUF + krow;
        const uint32_t sVb = sb + SV_OFF + buf * KBUF + vrow;

        CP_WAIT2();
        __syncthreads();
        if (kt + 3 < NKT) ISSUE_TILE(kt + 3, (kt + 3) & 3);
        CP_COMMIT();

        // ---- S = Q @ K^T : fp16 accumulators (2 packed regs per frag) ----
        uint32_t ch[2][4][2];
#pragma unroll
        for (int mb = 0; mb < 2; mb++)
#pragma unroll
            for (int n = 0; n < 4; n++) { ch[mb][n][0] = 0u; ch[mb][n][1] = 0u; }
#pragma unroll
        for (int kk = 0; kk < 8; kk++) {
            const uint32_t kcol = (uint32_t)(((2 * kk + b3) ^ l7) << 4);
#pragma unroll
            for (int np = 0; np < 2; np++) {
                uint32_t kf[4];
                ldsm4(kf, sKb + np * 4096 + kcol);
                mma16h(ch[0][2 * np],     qa[0][kk], kf[0], kf[1]);
                mma16h(ch[0][2 * np + 1], qa[0][kk], kf[2], kf[3]);
                mma16h(ch[1][2 * np],     qa[1][kk], kf[0], kf[1]);
                mma16h(ch[1][2 * np + 1], qa[1][kk], kf[2], kf[3]);
            }
        }

        // ---- softmax: unpack, P = exp2(s*C1 + C2) fp32 MUFU, repack ----
        uint32_t ph[2][4][2];
#pragma unroll
        for (int mb = 0; mb < 2; mb++) {
#pragma unroll
            for (int n = 0; n < 4; n++) {
                float2 f0 = __half22float2(*reinterpret_cast<__half2*>(&ch[mb][n][0]));
                float2 f1 = __half22float2(*reinterpret_cast<__half2*>(&ch[mb][n][1]));
                float e0 = ex2f(fmaf(f0.x, C1, C2));
                float e1 = ex2f(fmaf(f0.y, C1, C2));
                float e2 = ex2f(fmaf(f1.x, C1, C2));
                float e3 = ex2f(fmaf(f1.y, C1, C2));
                lacc[mb][0] += e0 + e1;
                lacc[mb][1] += e2 + e3;
                ph[mb][n][0] = pack_h2(e0, e1);
                ph[mb][n][1] = pack_h2(e2, e3);
                const int r1  = wm * 32 + mb * 16 + g;
                const int col = wn * 32 + n * 8 + 2 * t;
                const uint32_t cb = (uint32_t)(((col >> 3) ^ (r1 & 7)) << 4)
                                    + (uint32_t)((col & 7) * 2);
                *reinterpret_cast<uint32_t*>(smem + SP_OFF + r1 * 128 + cb) = ph[mb][n][0];
                const int r2 = r1 + 8;
                const uint32_t cb2 = (uint32_t)(((col >> 3) ^ (r2 & 7)) << 4)
                                     + (uint32_t)((col & 7) * 2);
                *reinterpret_cast<uint32_t*>(smem + SP_OFF + r2 * 128 + cb2) = ph[mb][n][1];
            }
        }

        // ---- PV own key-half (P in registers) — before the pair barrier ----
#pragma unroll
        for (int kb2 = 0; kb2 < 2; kb2++) {
            const int kb = wn * 2 + kb2;
            uint32_t vf[4][4];
#pragma unroll
            for (int j = 0; j < 4; j++)
                ldsm4t(vf[j], sVb + kb * 4096
                       + (uint32_t)(((2 * (wn * 4 + j) + hi) ^ l7) << 4));
#pragma unroll
            for (int mb = 0; mb < 2; mb++) {
                const int n0 = kb2 * 2;
                uint32_t pa[4] = { ph[mb][n0][0],     ph[mb][n0][1],
                                   ph[mb][n0 + 1][0], ph[mb][n0 + 1][1] };
#pragma unroll
                for (int j = 0; j < 4; j++) {
                    mma16(od[mb][2 * j],     pa, vf[j][0], vf[j][1]);
                    mma16(od[mb][2 * j + 1], pa, vf[j][2], vf[j][3]);
                }
            }
        }

        PAIR_BAR(1 + wm);

        // ---- PV other key-half (P from smem) ----
#pragma unroll
        for (int kb2 = 0; kb2 < 2; kb2++) {
            const int kb = (wn ^ 1) * 2 + kb2;
            uint32_t vf[4][4];
#pragma unroll
            for (int j = 0; j < 4; j++)
                ldsm4t(vf[j], sVb + kb * 4096
                       + (uint32_t)(((2 * (wn * 4 + j) + hi) ^ l7) << 4));
#pragma unroll
            for (int mb = 0; mb < 2; mb++) {
                uint32_t pa[4];
                ldsm4(pa, prow + (uint32_t)(mb * 16 * 128)
                          + (uint32_t)(((2 * kb + hi) ^ l7) << 4));
#pragma unroll
                for (int j = 0; j < 4; j++) {
                    mma16(od[mb][2 * j],     pa, vf[j][0], vf[j][1]);
                    mma16(od[mb][2 * j + 1], pa, vf[j][2], vf[j][3]);
                }
            }
        }
    }

    // ---- epilogue ----
#pragma unroll
    for (int mb = 0; mb < 2; mb++) {
        lacc[mb][0] += __shfl_xor_sync(0xffffffffu, lacc[mb][0], 1);
        lacc[mb][0] += __shfl_xor_sync(0xffffffffu, lacc[mb][0], 2);
        lacc[mb][1] += __shfl_xor_sync(0xffffffffu, lacc[mb][1], 1);
        lacc[mb][1] += __shfl_xor_sync(0xffffffffu, lacc[mb][1], 2);
    }
    if (t == 0) {
#pragma unroll
        for (int mb = 0; mb < 2; mb++) {
            sL[wn * 128 + wm * 32 + mb * 16 + g]     = lacc[mb][0];
            sL[wn * 128 + wm * 32 + mb * 16 + g + 8] = lacc[mb][1];
        }
    }
    __syncthreads();

#pragma unroll
    for (int mb = 0; mb < 2; mb++) {
        const int r1 = wm * 32 + mb * 16 + g;
        const int r2 = r1 + 8;
        const float inv1 = 1.0f / (sL[r1] + sL[128 + r1]);
        const float inv2 = 1.0f / (sL[r2] + sL[128 + r2]);
        const bool m1 = (q0 + r1) >= vl;
        const bool m2 = (q0 + r2) >= vl;
#pragma unroll
        for (int dt = 0; dt < 8; dt++) {
            const int col = wn * 64 + dt * 8 + 2 * t;
            float2 v1, v2;
            if (m1) { v1.x = g_meanV[b * Dn + col] * invK; v1.y = g_meanV[b * Dn + col + 1] * invK; }
            else    { v1.x = od[mb][dt][0] * inv1;         v1.y = od[mb][dt][1] * inv1; }
            if (m2) { v2.x = g_meanV[b * Dn + col] * invK; v2.y = g_meanV[b * Dn + col + 1] * invK; }
            else    { v2.x = od[mb][dt][2] * inv2;         v2.y = od[mb][dt][3] * inv2; }
            *reinterpret_cast<float2*>(&Ob[(size_t)r1 * Dn + col]) = v1;
            *reinterpret_cast<float2*>(&Ob[(size_t)r2 * Dn + col]) = v2;
        }
    }
#undef ISSUE_TILE
}

// ------------------------------------------------------------------
extern "C" void kernel_launch(void* const* d_in, const int* in_sizes, int n_in,
                              void* d_out, int out_size)
{
    const float* q  = (const float*)d_in[0];
    const float* k  = (const float*)d_in[1];
    const float* v  = (const float*)d_in[2];
    const int*   vl = (const int*)d_in[3];
    float* out = (float*)d_out;

    cudaFuncSetAttribute(flash_kernel,
                         cudaFuncAttributeMaxDynamicSharedMemorySize, SMEM_TOTAL);

    void* mv_ptr = nullptr;
    cudaGetSymbolAddress(&mv_ptr, g_meanV);
    cudaMemsetAsync(mv_ptr, 0, Bn * Dn * sizeof(float));

    convert_kernel<<<4096, 256>>>(k, v);
    flash_kernel<<<dim3(Qn / QT, Bn), NTHREADS, SMEM_TOTAL>>>(q, vl, out);
}

// round 17
// speedup vs baseline: 1.1893x; 1.1893x over previous
#include <cuda_runtime.h>
#include <cuda_fp16.h>
#include <cstdint>

#define Bn 16
#define Qn 2048
#define Kn 2048
#define Dn 128
#define QT 128
#define KT 64
#define NKT 32
#define NTHREADS 256
#define SCALE 0.08838834764831845f

// smem: fp16 K/V tiles 256B rows, XOR swizzle (c16 ^= r&7)
#define SQ_OFF 0            // Q: 128 x 256B = 32768
#define SK_OFF 32768        // K: 4 bufs x 16384 = 65536
#define SV_OFF 98304        // V: 4 bufs x 16384 = 65536
#define SP_OFF 163840       // P: 128 x 128B = 16384 (fp16, swizzled)
#define SL_OFF 180224       // l partials: 2 x 128 floats = 1024
#define SMEM_TOTAL 181248
#define KBUF 16384

__device__ __half KH[(size_t)Bn * Kn * Dn];
__device__ __half VH[(size_t)Bn * Kn * Dn];
__device__ float g_meanV[Bn * Dn];            // per-batch column SUMS of V

// ------------------------------------------------------------------ helpers
__device__ __forceinline__ uint32_t smem_u32(const void* p) {
    uint32_t a;
    asm("{ .reg .u64 t; cvta.to.shared.u64 t, %1; cvt.u32.u64 %0, t; }"
        : "=r"(a) : "l"(p));
    return a;
}
__device__ __forceinline__ float ex2f(float x) {
    float y; asm("ex2.approx.ftz.f32 %0, %1;" : "=f"(y) : "f"(x)); return y;
}
__device__ __forceinline__ uint32_t pack_h2(float lo, float hi) {
    __half2 h = __floats2half2_rn(lo, hi);
    return *reinterpret_cast<uint32_t*>(&h);
}
__device__ __forceinline__ void mma16(float* c, const uint32_t* a,
                                      uint32_t b0, uint32_t b1) {
    asm volatile(
        "mma.sync.aligned.m16n8k16.row.col.f32.f16.f16.f32 "
        "{%0,%1,%2,%3}, {%4,%5,%6,%7}, {%8,%9}, {%0,%1,%2,%3};\n"
        : "+f"(c[0]), "+f"(c[1]), "+f"(c[2]), "+f"(c[3])
        : "r"(a[0]), "r"(a[1]), "r"(a[2]), "r"(a[3]), "r"(b0), "r"(b1));
}
__device__ __forceinline__ void ldsm4(uint32_t* r, uint32_t addr) {
    asm volatile("ldmatrix.sync.aligned.m8n8.x4.shared.b16 {%0,%1,%2,%3}, [%4];"
                 : "=r"(r[0]), "=r"(r[1]), "=r"(r[2]), "=r"(r[3]) : "r"(addr));
}
__device__ __forceinline__ void ldsm4t(uint32_t* r, uint32_t addr) {
    asm volatile("ldmatrix.sync.aligned.m8n8.x4.trans.shared.b16 {%0,%1,%2,%3}, [%4];"
                 : "=r"(r[0]), "=r"(r[1]), "=r"(r[2]), "=r"(r[3]) : "r"(addr));
}
__device__ __forceinline__ void cpa16(uint32_t dst, const void* src) {
    asm volatile("cp.async.cg.shared.global [%0], [%1], 16;"
                 :: "r"(dst), "l"(src) : "memory");
}
#define CP_COMMIT() asm volatile("cp.async.commit_group;" ::: "memory")
#define CP_WAIT2()  asm volatile("cp.async.wait_group 2;"  ::: "memory")
#define PAIR_BAR(id) asm volatile("bar.sync %0, 64;" :: "r"(id) : "memory")

// ------------------------------------------------------------------ prep
// K,V fp32->fp16 + V column partial sums. 1024 blocks x 512 threads x
// 2 float4 = 1,048,576 float4 = exactly Bn*Kn*Dn/4. Each block covers 32
// V-rows (batch = blockIdx.x >> 6; 64 blocks per batch). Private smem slots
// (no smem atomics), then conflict-free stride-128 reduction.
__global__ void convert_kernel(const float* __restrict__ K,
                               const float* __restrict__ V) {
    __shared__ float sh[32 * 128];
    const int tid = threadIdx.x;

    const size_t base = (size_t)blockIdx.x * 1024;    // float4 index
#pragma unroll
    for (int j = 0; j < 2; j++) {
        const size_t i = base + j * 512 + tid;
        float4 k4 = reinterpret_cast<const float4*>(K)[i];
        float4 v4 = reinterpret_cast<const float4*>(V)[i];
        uint2 uk = { pack_h2(k4.x, k4.y), pack_h2(k4.z, k4.w) };
        uint2 uv = { pack_h2(v4.x, v4.y), pack_h2(v4.z, v4.w) };
        reinterpret_cast<uint2*>(KH)[i] = uk;
        reinterpret_cast<uint2*>(VH)[i] = uv;
        // private slot: row (0..31), col quad (0..31)
        const int e = j * 512 + tid;
        const int r = e >> 5;
        const int c = (e & 31) * 4;
        float* s = &sh[r * 128 + c];
        s[0] = v4.x; s[1] = v4.y; s[2] = v4.z; s[3] = v4.w;
    }
    __syncthreads();

    if (tid < 128) {
        float s = 0.f;
#pragma unroll
        for (int r = 0; r < 32; r++) s += sh[r * 128 + tid];
        atomicAdd(&g_meanV[(blockIdx.x >> 6) * 128 + tid], s);
    }
}

// ------------------------------------------------------------------ flash
// CTA = (128-q tile, batch). wm = warp>>1, wn = warp&1 (exchange pairs on
// adjacent SMSPs; named pair barrier). QK + PV both fp32-accum fp16 MMA.
__global__ void __launch_bounds__(NTHREADS, 1)
flash_kernel(const float* __restrict__ Qg, const int* __restrict__ VL,
             float* __restrict__ Og)
{
    const int b    = blockIdx.y;
    const int q0   = blockIdx.x * QT;
    const int tid  = threadIdx.x;
    const int warp = tid >> 5;
    const int wm   = warp >> 1;       // row-block (32 rows)
    const int wn   = warp & 1;        // key-half / d-half
    const int lane = tid & 31;
    const int g    = lane >> 2;
    const int t    = lane & 3;
    const int l7   = lane & 7;
    const int b3   = (lane >> 3) & 1;
    const int hi   = lane >> 4;
    const int vl   = VL[b];
    const float invK = 1.0f / (float)Kn;
    float* Ob = Og + ((size_t)b * Qn + q0) * Dn;

    // Fully masked tile -> meanV
    if (q0 >= vl) {
        for (int r = warp; r < QT; r += 8) {
            int c = lane * 4;
            float4 m = *reinterpret_cast<const float4*>(&g_meanV[b * Dn + c]);
            m.x *= invK; m.y *= invK; m.z *= invK; m.w *= invK;
            *reinterpret_cast<float4*>(&Ob[(size_t)r * Dn + c]) = m;
        }
        return;
    }

    extern __shared__ char smem[];
    const uint32_t sb = smem_u32(smem);
    float* sL = reinterpret_cast<float*>(smem + SL_OFF);
    const __half* Kb = KH + (size_t)b * Kn * Dn;
    const __half* Vb = VH + (size_t)b * Kn * Dn;

#define ISSUE_TILE(kt_, bf_) do {                                              \
        const __half* ks_ = Kb + (size_t)(kt_) * KT * Dn;                       \
        const __half* vs_ = Vb + (size_t)(kt_) * KT * Dn;                       \
        _Pragma("unroll")                                                       \
        for (int j_ = 0; j_ < 4; j_++) {                                        \
            int id_ = j_ * 256 + tid;                                           \
            int r_ = id_ >> 4, c_ = id_ & 15;                                   \
            uint32_t off_ = (uint32_t)(r_ * 256 + ((c_ ^ (r_ & 7)) << 4));      \
            cpa16(sb + SK_OFF + (bf_) * KBUF + off_, ks_ + r_ * 128 + c_ * 8);  \
            cpa16(sb + SV_OFF + (bf_) * KBUF + off_, vs_ + r_ * 128 + c_ * 8);  \
        }                                                                       \
    } while (0)

    // prologue: tiles 0..2 in flight; stage Q; load persistent Q frags
    ISSUE_TILE(0, 0); CP_COMMIT();
    ISSUE_TILE(1, 1); CP_COMMIT();
    ISSUE_TILE(2, 2); CP_COMMIT();
    {
        const float4* Qs = reinterpret_cast<const float4*>(
            Qg + ((size_t)b * Qn + q0) * Dn);
#pragma unroll
        for (int j = 0; j < 16; j++) {
            int f = j * 256 + tid;
            int row = f >> 5, d4 = f & 31;
            float4 x = Qs[f];
            uint2 u = { pack_h2(x.x, x.y), pack_h2(x.z, x.w) };
            int c16 = d4 >> 1;
            uint32_t byte = (uint32_t)(row * 256 + ((c16 ^ (row & 7)) << 4)
                                       + (d4 & 1) * 8);
            *reinterpret_cast<uint2*>(smem + SQ_OFF + byte) = u;
        }
    }
    __syncthreads();

    uint32_t qa[2][8][4];   // [m-block][k-step]
#pragma unroll
    for (int mb = 0; mb < 2; mb++) {
        const uint32_t qrow = sb + SQ_OFF
            + (uint32_t)((wm * 32 + mb * 16 + b3 * 8 + l7) * 256);
#pragma unroll
        for (int kk = 0; kk < 8; kk++)
            ldsm4(qa[mb][kk], qrow + (uint32_t)(((2 * kk + hi) ^ l7) << 4));
    }

    const uint32_t krow = (uint32_t)((hi * 8 + l7) * 256) + (uint32_t)(wn * 8192);
    const uint32_t vrow = (uint32_t)((b3 * 8 + l7) * 256);
    const uint32_t prow = sb + SP_OFF + (uint32_t)((wm * 32 + b3 * 8 + l7) * 128);

    const float C1 = SCALE * 1.4426950408889634f;
    const float C2 = -8.0f * 1.4426950408889634f;

    float od[2][8][4];
#pragma unroll
    for (int mb = 0; mb < 2; mb++)
#pragma unroll
        for (int i = 0; i < 8; i++)
            od[mb][i][0] = od[mb][i][1] = od[mb][i][2] = od[mb][i][3] = 0.f;
    float lacc[2][2] = {{0.f, 0.f}, {0.f, 0.f}};

    for (int kt = 0; kt < NKT; kt++) {
        const int buf = kt & 3;
        const uint32_t sKb = sb + SK_OFF + buf * KBUF + krow;
        const uint32_t sVb = sb + SV_OFF + buf * KBUF + vrow;

        CP_WAIT2();
        __syncthreads();     // all warps done with tile kt-1: ring + P safe
        if (kt + 3 < NKT) ISSUE_TILE(kt + 3, (kt + 3) & 3);
        CP_COMMIT();

        // ---- S = Q @ K^T : 32 rows x 32 keys per warp (fp32 accum) ----
        float c[2][4][4];
#pragma unroll
        for (int mb = 0; mb < 2; mb++)
#pragma unroll
            for (int n = 0; n < 4; n++)
                c[mb][n][0] = c[mb][n][1] = c[mb][n][2] = c[mb][n][3] = 0.f;
#pragma unroll
        for (int kk = 0; kk < 8; kk++) {
            const uint32_t kcol = (uint32_t)(((2 * kk + b3) ^ l7) << 4);
#pragma unroll
            for (int np = 0; np < 2; np++) {
                uint32_t kf[4];
                ldsm4(kf, sKb + np * 4096 + kcol);
                mma16(c[0][2 * np],     qa[0][kk], kf[0], kf[1]);
                mma16(c[0][2 * np + 1], qa[0][kk], kf[2], kf[3]);
                mma16(c[1][2 * np],     qa[1][kk], kf[0], kf[1]);
                mma16(c[1][2 * np + 1], qa[1][kk], kf[2], kf[3]);
            }
        }

        // ---- softmax: P = exp2(s*C1 + C2) (fp32 MUFU); write P to smem ----
        uint32_t ph[2][4][2];
#pragma unroll
        for (int mb = 0; mb < 2; mb++) {
#pragma unroll
            for (int n = 0; n < 4; n++) {
                float e0 = ex2f(fmaf(c[mb][n][0], C1, C2));
                float e1 = ex2f(fmaf(c[mb][n][1], C1, C2));
                float e2 = ex2f(fmaf(c[mb][n][2], C1, C2));
                float e3 = ex2f(fmaf(c[mb][n][3], C1, C2));
                lacc[mb][0] += e0 + e1;
                lacc[mb][1] += e2 + e3;
                ph[mb][n][0] = pack_h2(e0, e1);
                ph[mb][n][1] = pack_h2(e2, e3);
                const int r1  = wm * 32 + mb * 16 + g;
                const int col = wn * 32 + n * 8 + 2 * t;
                const uint32_t cb = (uint32_t)(((col >> 3) ^ (r1 & 7)) << 4)
                                    + (uint32_t)((col & 7) * 2);
                *reinterpret_cast<uint32_t*>(smem + SP_OFF + r1 * 128 + cb) = ph[mb][n][0];
                const int r2 = r1 + 8;
                const uint32_t cb2 = (uint32_t)(((col >> 3) ^ (r2 & 7)) << 4)
                                     + (uint32_t)((col & 7) * 2);
                *reinterpret_cast<uint32_t*>(smem + SP_OFF + r2 * 128 + cb2) = ph[mb][n][1];
            }
        }

        // ---- PV own key-half (P in registers) — before the pair barrier ----
#pragma unroll
        for (int kb2 = 0; kb2 < 2; kb2++) {
            const int kb = wn * 2 + kb2;
            uint32_t vf[4][4];
#pragma unroll
            for (int j = 0; j < 4; j++)
                ldsm4t(vf[j], sVb + kb * 4096
                       + (uint32_t)(((2 * (wn * 4 + j) + hi) ^ l7) << 4));
#pragma unroll
            for (int mb = 0; mb < 2; mb++) {
                const int n0 = kb2 * 2;
                uint32_t pa[4] = { ph[mb][n0][0],     ph[mb][n0][1],
                                   ph[mb][n0 + 1][0], ph[mb][n0 + 1][1] };
#pragma unroll
                for (int j = 0; j < 4; j++) {
                    mma16(od[mb][2 * j],     pa, vf[j][0], vf[j][1]);
                    mma16(od[mb][2 * j + 1], pa, vf[j][2], vf[j][3]);
                }
            }
        }

        PAIR_BAR(1 + wm);    // only the 2-warp exchange pair syncs here

        // ---- PV other key-half (P from smem) ----
#pragma unroll
        for (int kb2 = 0; kb2 < 2; kb2++) {
            const int kb = (wn ^ 1) * 2 + kb2;
            uint32_t vf[4][4];
#pragma unroll
            for (int j = 0; j < 4; j++)
                ldsm4t(vf[j], sVb + kb * 4096
                       + (uint32_t)(((2 * (wn * 4 + j) + hi) ^ l7) << 4));
#pragma unroll
            for (int mb = 0; mb < 2; mb++) {
                uint32_t pa[4];
                ldsm4(pa, prow + (uint32_t)(mb * 16 * 128)
                          + (uint32_t)(((2 * kb + hi) ^ l7) << 4));
#pragma unroll
                for (int j = 0; j < 4; j++) {
                    mma16(od[mb][2 * j],     pa, vf[j][0], vf[j][1]);
                    mma16(od[mb][2 * j + 1], pa, vf[j][2], vf[j][3]);
                }
            }
        }
    }

    // ---- epilogue: cross-warp l reduction, normalize, store ----
#pragma unroll
    for (int mb = 0; mb < 2; mb++) {
        lacc[mb][0] += __shfl_xor_sync(0xffffffffu, lacc[mb][0], 1);
        lacc[mb][0] += __shfl_xor_sync(0xffffffffu, lacc[mb][0], 2);
        lacc[mb][1] += __shfl_xor_sync(0xffffffffu, lacc[mb][1], 1);
        lacc[mb][1] += __shfl_xor_sync(0xffffffffu, lacc[mb][1], 2);
    }
    if (t == 0) {
#pragma unroll
        for (int mb = 0; mb < 2; mb++) {
            sL[wn * 128 + wm * 32 + mb * 16 + g]     = lacc[mb][0];
            sL[wn * 128 + wm * 32 + mb * 16 + g + 8] = lacc[mb][1];
        }
    }
    __syncthreads();

#pragma unroll
    for (int mb = 0; mb < 2; mb++) {
        const int r1 = wm * 32 + mb * 16 + g;
        const int r2 = r1 + 8;
        const float inv1 = 1.0f / (sL[r1] + sL[128 + r1]);
        const float inv2 = 1.0f / (sL[r2] + sL[128 + r2]);
        const bool m1 = (q0 + r1) >= vl;
        const bool m2 = (q0 + r2) >= vl;
#pragma unroll
        for (int dt = 0; dt < 8; dt++) {
            const int col = wn * 64 + dt * 8 + 2 * t;
            float2 v1, v2;
            if (m1) { v1.x = g_meanV[b * Dn + col] * invK; v1.y = g_meanV[b * Dn + col + 1] * invK; }
            else    { v1.x = od[mb][dt][0] * inv1;         v1.y = od[mb][dt][1] * inv1; }
            if (m2) { v2.x = g_meanV[b * Dn + col] * invK; v2.y = g_meanV[b * Dn + col + 1] * invK; }
            else    { v2.x = od[mb][dt][2] * inv2;         v2.y = od[mb][dt][3] * inv2; }
            *reinterpret_cast<float2*>(&Ob[(size_t)r1 * Dn + col]) = v1;
            *reinterpret_cast<float2*>(&Ob[(size_t)r2 * Dn + col]) = v2;
        }
    }
#undef ISSUE_TILE
}

// ------------------------------------------------------------------
extern "C" void kernel_launch(void* const* d_in, const int* in_sizes, int n_in,
                              void* d_out, int out_size)
{
    const float* q  = (const float*)d_in[0];
    const float* k  = (const float*)d_in[1];
    const float* v  = (const float*)d_in[2];
    const int*   vl = (const int*)d_in[3];
    float* out = (float*)d_out;

    cudaFuncSetAttribute(flash_kernel,
                         cudaFuncAttributeMaxDynamicSharedMemorySize, SMEM_TOTAL);

    // zero meanV accumulators via memset node (replay-safe, no extra kernel)
    void* mv_ptr = nullptr;
    cudaGetSymbolAddress(&mv_ptr, g_meanV);
    cudaMemsetAsync(mv_ptr, 0, Bn * Dn * sizeof(float));

    convert_kernel<<<1024, 512>>>(k, v);
    flash_kernel<<<dim3(Qn / QT, Bn), NTHREADS, SMEM_TOTAL>>>(q, vl, out);
}